// round 12
// baseline (speedup 1.0000x reference)
#include <cuda_runtime.h>
#include <cuda_bf16.h>
#include <math.h>

typedef unsigned int u32;
typedef unsigned short u16;

#define D_MODEL 1024
#define NHEAD   16
#define DEPTH   64
#define BATCH   4
#define SEQ     2048
#define MROWS   (BATCH * SEQ)       // 8192
#define NBH     (BATCH * NHEAD)     // 64
#define INN     (MROWS * D_MODEL)   // 8388608
#define WN      (D_MODEL * D_MODEL)
#define PROJN   (NBH * SEQ * DEPTH) // 8388608
#define QSCALE  (0.125f * 1.44269504088896341f)   // 1/sqrt(64) * log2(e)

// ---------------- global scratch (alloc-free rule) -------------------------
__device__ u16 g_xh[3][INN],  g_xl[3][INN];    // split q/k/v inputs
__device__ u16 g_wh[4][WN],   g_wl[4][WN];     // split wq/wk/wv/wo [k][n]
__device__ u16 g_ph[3][PROJN], g_pl[3][PROJN]; // projected qh/kh/vh planes
__device__ u16 g_oh[INN],     g_ol[INN];       // attention output planes
__device__ float g_u[2][PROJN];                // split-K unnormalized sums
__device__ float g_l[2][NBH * SEQ];            // split-K exp sums

// ---------------- primitives ----------------------------------------------
__device__ __forceinline__ void mma_bf16(float c[4], const u32 a[4], const u32 b[2])
{
    asm("mma.sync.aligned.m16n8k16.row.col.f32.bf16.bf16.f32 "
        "{%0,%1,%2,%3}, {%4,%5,%6,%7}, {%8,%9}, {%0,%1,%2,%3};"
        : "+f"(c[0]), "+f"(c[1]), "+f"(c[2]), "+f"(c[3])
        : "r"(a[0]), "r"(a[1]), "r"(a[2]), "r"(a[3]), "r"(b[0]), "r"(b[1]));
}

struct HL { u32 h, l; };
__device__ __forceinline__ HL split2f(float x, float y)
{
    HL r;
    asm("cvt.rn.bf16x2.f32 %0, %1, %2;" : "=r"(r.h) : "f"(y), "f"(x));
    float xh = __uint_as_float(r.h << 16);
    float yh = __uint_as_float(r.h & 0xffff0000u);
    asm("cvt.rn.bf16x2.f32 %0, %1, %2;" : "=r"(r.l) : "f"(y - yh), "f"(x - xh));
    return r;
}

__device__ __forceinline__ float ex2(float x)
{
    float y;
    asm("ex2.approx.ftz.f32 %0, %1;" : "=f"(y) : "f"(x));
    return y;
}

__device__ __forceinline__ void ldsm4(u32 r[4], u32 a)
{
    asm volatile("ldmatrix.sync.aligned.m8n8.x4.shared.b16 {%0,%1,%2,%3}, [%4];"
        : "=r"(r[0]), "=r"(r[1]), "=r"(r[2]), "=r"(r[3]) : "r"(a));
}
__device__ __forceinline__ void ldsm4t(u32 r[4], u32 a)
{
    asm volatile("ldmatrix.sync.aligned.m8n8.x4.trans.shared.b16 {%0,%1,%2,%3}, [%4];"
        : "=r"(r[0]), "=r"(r[1]), "=r"(r[2]), "=r"(r[3]) : "r"(a));
}
__device__ __forceinline__ void cpa16(u32 s, const void* g)
{
    asm volatile("cp.async.ca.shared.global [%0], [%1], 16;" :: "r"(s), "l"(g));
}
#define CP_COMMIT() asm volatile("cp.async.commit_group;" ::: "memory")
#define CP_WAIT1()  asm volatile("cp.async.wait_group 1;" ::: "memory")
#define CP_WAIT0()  asm volatile("cp.async.wait_group 0;" ::: "memory")

// ---------------- split pre-passes (fused across tensors) ------------------
__global__ void split3_kernel(const float4* __restrict__ s0,
                              const float4* __restrict__ s1,
                              const float4* __restrict__ s2,
                              uint2* __restrict__ hi, uint2* __restrict__ lo, int n4)
{
    const int z = blockIdx.z;
    const float4* src = (z == 0) ? s0 : (z == 1) ? s1 : s2;
    uint2* h = hi + (size_t)z * n4;
    uint2* l = lo + (size_t)z * n4;
    int i = blockIdx.x * blockDim.x + threadIdx.x;
    const int stride = gridDim.x * blockDim.x;
    for (; i < n4; i += stride) {
        float4 v = src[i];
        HL a = split2f(v.x, v.y), b = split2f(v.z, v.w);
        h[i] = make_uint2(a.h, b.h);
        l[i] = make_uint2(a.l, b.l);
    }
}

__global__ void split4_kernel(const float4* __restrict__ s0,
                              const float4* __restrict__ s1,
                              const float4* __restrict__ s2,
                              const float4* __restrict__ s3,
                              uint2* __restrict__ hi, uint2* __restrict__ lo, int n4)
{
    const int z = blockIdx.z;
    const float4* src = (z == 0) ? s0 : (z == 1) ? s1 : (z == 2) ? s2 : s3;
    uint2* h = hi + (size_t)z * n4;
    uint2* l = lo + (size_t)z * n4;
    int i = blockIdx.x * blockDim.x + threadIdx.x;
    const int stride = gridDim.x * blockDim.x;
    for (; i < n4; i += stride) {
        float4 v = src[i];
        HL a = split2f(v.x, v.y), b = split2f(v.z, v.w);
        h[i] = make_uint2(a.h, b.h);
        l[i] = make_uint2(a.l, b.l);
    }
}

// ---------------- GEMM core (HMMA, 2-stage, R6-proven) ---------------------
#define BKP 40
#define NPW 136
#define ASZ (128 * BKP)               // 5120
#define WSZ (32 * NPW)                // 4352
#define GBUF (2 * ASZ + 2 * WSZ)      // 18944 elems per buffer

__device__ __forceinline__ void gemm_stage(
    u32 sbase, int buf,
    const u16* __restrict__ Ah_g, const u16* __restrict__ Al_g,
    const u16* __restrict__ Wh_g, const u16* __restrict__ Wl_g,
    int m0, int n0, int kt, int tid)
{
    const u32 db = sbase + buf * (GBUF * 2);
    const int a_row = tid >> 2, a_off = tid & 3;
    const int w_row = tid >> 4, w_off = tid & 15;
#pragma unroll
    for (int i = 0; i < 4; i++) {
        const u16* src = (i < 2) ? Ah_g : Al_g;
        const int row = a_row + 64 * (i & 1);
        cpa16(db + 2 * ((i >> 1) * ASZ + row * BKP + a_off * 8),
              src + (size_t)(m0 + row) * D_MODEL + kt * 32 + a_off * 8);
    }
#pragma unroll
    for (int i = 0; i < 4; i++) {
        const u16* src = (i < 2) ? Wh_g : Wl_g;
        const int row = w_row + 16 * (i & 1);
        cpa16(db + 2 * (2 * ASZ + (i >> 1) * WSZ + row * NPW + w_off * 8),
              src + (size_t)(kt * 32 + row) * D_MODEL + n0 + w_off * 8);
    }
    CP_COMMIT();
}

template <int MODE>
__device__ __forceinline__ void gemm_body(
    const u16* __restrict__ Ah_g, const u16* __restrict__ Al_g,
    const u16* __restrict__ Wh_g, const u16* __restrict__ Wl_g,
    const float* __restrict__ bias, float scale,
    float* __restrict__ Cf, u16* __restrict__ Ch, u16* __restrict__ Cl)
{
    extern __shared__ u16 smw[];
    const u32 sbase = (u32)__cvta_generic_to_shared(smw);

    const int m0 = blockIdx.y * 128, n0 = blockIdx.x * 128;
    const int tid = threadIdx.x, lane = tid & 31, warp = tid >> 5;
    const int g = lane >> 2, tig = lane & 3;
    const int wm = warp >> 2, wn = warp & 3;

    const int rA = wm * 64 + (lane & 7) + ((lane >> 3) & 1) * 8;
    const int cA = (lane >> 4) * 8;
    const int rW = ((lane >> 3) & 1) * 8 + (lane & 7);
    const int cW = wn * 32 + (lane >> 4) * 8;

    float acc[4][4][4];
#pragma unroll
    for (int i = 0; i < 4; i++)
#pragma unroll
        for (int j = 0; j < 4; j++)
#pragma unroll
            for (int c = 0; c < 4; c++) acc[i][j][c] = 0.f;

    gemm_stage(sbase, 0, Ah_g, Al_g, Wh_g, Wl_g, m0, n0, 0, tid);

    for (int kt = 0; kt < 32; kt++) {
        const int buf = kt & 1;
        if (kt < 31) {
            gemm_stage(sbase, buf ^ 1, Ah_g, Al_g, Wh_g, Wl_g, m0, n0, kt + 1, tid);
            CP_WAIT1();
        } else {
            CP_WAIT0();
        }
        __syncthreads();

        const u32 db = sbase + buf * (GBUF * 2);
#pragma unroll
        for (int kk = 0; kk < 2; kk++) {
            u32 ah[4][4], al_[4][4];
#pragma unroll
            for (int ma = 0; ma < 4; ma++) {
                const u32 a = db + 2 * ((rA + ma * 16) * BKP + kk * 16 + cA);
                ldsm4(ah[ma], a);
                ldsm4(al_[ma], a + 2 * ASZ);
            }
            u32 bh[4][2], bl[4][2];
#pragma unroll
            for (int np = 0; np < 2; np++) {
                const u32 a = db + 2 * (2 * ASZ + (kk * 16 + rW) * NPW + cW + np * 16);
                u32 r[4];
                ldsm4t(r, a);
                bh[2*np][0] = r[0]; bh[2*np][1] = r[1];
                bh[2*np+1][0] = r[2]; bh[2*np+1][1] = r[3];
                ldsm4t(r, a + 2 * WSZ);
                bl[2*np][0] = r[0]; bl[2*np][1] = r[1];
                bl[2*np+1][0] = r[2]; bl[2*np+1][1] = r[3];
            }
#pragma unroll
            for (int ma = 0; ma < 4; ma++)
#pragma unroll
                for (int na = 0; na < 4; na++) {
                    mma_bf16(acc[ma][na], ah[ma], bh[na]);
                    mma_bf16(acc[ma][na], ah[ma], bl[na]);
                    mma_bf16(acc[ma][na], al_[ma], bh[na]);
                }
        }
        __syncthreads();
    }

#pragma unroll
    for (int ma = 0; ma < 4; ma++) {
        const int m_r = m0 + wm * 64 + ma * 16 + g;
#pragma unroll
        for (int na = 0; na < 4; na++) {
            const int n = n0 + wn * 32 + na * 8 + 2 * tig;
            const float2 bv = *(const float2*)&bias[n];
            const float o0 = (acc[ma][na][0] + bv.x) * scale;
            const float o1 = (acc[ma][na][1] + bv.y) * scale;
            const float o2 = (acc[ma][na][2] + bv.x) * scale;
            const float o3 = (acc[ma][na][3] + bv.y) * scale;
            if (MODE == 0) {
                *(float2*)&Cf[(size_t)m_r * D_MODEL + n] = make_float2(o0, o1);
                *(float2*)&Cf[(size_t)(m_r + 8) * D_MODEL + n] = make_float2(o2, o3);
            } else {
                const int h = n >> 6, d = n & 63;
                const int b = m_r >> 11, s = m_r & 2047;
                const size_t i0 = (((size_t)(b * NHEAD + h)) * SEQ + s) * DEPTH + d;
                const size_t i1 = i0 + 8 * DEPTH;
                HL r0 = split2f(o0, o1), r1 = split2f(o2, o3);
                *(u32*)&Ch[i0] = r0.h; *(u32*)&Cl[i0] = r0.l;
                *(u32*)&Ch[i1] = r1.h; *(u32*)&Cl[i1] = r1.l;
            }
        }
    }
}

__global__ void __launch_bounds__(256, 2) gemm_proj(
    const u16* __restrict__ xh, const u16* __restrict__ xl,
    const u16* __restrict__ wh, const u16* __restrict__ wl,
    const float* __restrict__ bq, const float* __restrict__ bk,
    const float* __restrict__ bv,
    u16* __restrict__ ph, u16* __restrict__ pl)
{
    const int z = blockIdx.z;
    const float* bias = (z == 0) ? bq : (z == 1) ? bk : bv;
    gemm_body<1>(xh + (size_t)z * INN, xl + (size_t)z * INN,
                 wh + (size_t)z * WN,  wl + (size_t)z * WN,
                 bias, (z == 0) ? QSCALE : 1.f,
                 nullptr, ph + (size_t)z * PROJN, pl + (size_t)z * PROJN);
}

__global__ void __launch_bounds__(256, 2) gemm_out(
    const u16* __restrict__ Ah, const u16* __restrict__ Al,
    const u16* __restrict__ Wh, const u16* __restrict__ Wl,
    const float* __restrict__ bias, float* __restrict__ Cf)
{
    gemm_body<0>(Ah, Al, Wh, Wl, bias, 1.f, Cf, nullptr, nullptr);
}

// ---------------- flash attention (HMMA, no-max softmax, split-K 2-way) -----
// blockIdx.z selects the key half. Each CTA writes unnormalized U (fp32) and
// exp-sum L; a combine kernel merges halves (valid because softmax is max-free:
// both halves share the same implicit scale).
#define KP  72
#define PS  (64 * KP)
#define ABUFE (4 * PS)

__device__ __forceinline__ void attn_stage(
    u32 sbase, int buf,
    const u16* __restrict__ Kh_g, const u16* __restrict__ Kl_g,
    const u16* __restrict__ Vh_g, const u16* __restrict__ Vl_g,
    int bh, int kc, int tid)
{
    const u32 db = sbase + buf * (ABUFE * 2);
#pragma unroll
    for (int i = 0; i < 8; i++) {
        const int plane = i >> 1;
        const u16* src = (plane == 0) ? Kh_g : (plane == 1) ? Kl_g
                       : (plane == 2) ? Vh_g : Vl_g;
        const int row = (tid >> 3) + 32 * (i & 1);
        cpa16(db + 2 * (plane * PS + row * KP + (tid & 7) * 8),
              src + ((size_t)bh * SEQ + kc + row) * DEPTH + (tid & 7) * 8);
    }
    CP_COMMIT();
}

__global__ void __launch_bounds__(256, 2) attn_tc(
    const u16* __restrict__ Qh_g, const u16* __restrict__ Ql_g,
    const u16* __restrict__ Kh_g, const u16* __restrict__ Kl_g,
    const u16* __restrict__ Vh_g, const u16* __restrict__ Vl_g,
    float* __restrict__ U, float* __restrict__ L)
{
    extern __shared__ u16 sma[];
    const u32 sbase = (u32)__cvta_generic_to_shared(sma);

    const int bh = blockIdx.y, q0 = blockIdx.x * 128, z = blockIdx.z;
    const int kbase = z * (SEQ / 2);
    const int tid = threadIdx.x, lane = tid & 31, warp = tid >> 5;
    const int g = lane >> 2, tig = lane & 3;
    const int w16 = warp * 16;

    u32 qfh[4][4], qfl[4][4];
    {
        const u16* Qbh = Qh_g + ((size_t)bh * SEQ + q0) * DEPTH;
        const u16* Qbl = Ql_g + ((size_t)bh * SEQ + q0) * DEPTH;
#pragma unroll
        for (int ks = 0; ks < 4; ks++) {
            const int c = ks * 16 + 2 * tig;
            qfh[ks][0] = *(const u32*)&Qbh[(w16 + g) * DEPTH + c];
            qfh[ks][1] = *(const u32*)&Qbh[(w16 + g + 8) * DEPTH + c];
            qfh[ks][2] = *(const u32*)&Qbh[(w16 + g) * DEPTH + c + 8];
            qfh[ks][3] = *(const u32*)&Qbh[(w16 + g + 8) * DEPTH + c + 8];
            qfl[ks][0] = *(const u32*)&Qbl[(w16 + g) * DEPTH + c];
            qfl[ks][1] = *(const u32*)&Qbl[(w16 + g + 8) * DEPTH + c];
            qfl[ks][2] = *(const u32*)&Qbl[(w16 + g) * DEPTH + c + 8];
            qfl[ks][3] = *(const u32*)&Qbl[(w16 + g + 8) * DEPTH + c + 8];
        }
    }

    float o[8][4];
#pragma unroll
    for (int na = 0; na < 8; na++)
#pragma unroll
        for (int c = 0; c < 4; c++) o[na][c] = 0.f;
    float l0 = 0.f, l1 = 0.f;

    const int rK = (lane >> 4) * 8 + (lane & 7);
    const int cK = ((lane >> 3) & 1) * 8;
    const int rV = ((lane >> 3) & 1) * 8 + (lane & 7);
    const int cV = (lane >> 4) * 8;

    attn_stage(sbase, 0, Kh_g, Kl_g, Vh_g, Vl_g, bh, kbase, tid);

    const int kend = kbase + SEQ / 2;
    for (int kc = kbase; kc < kend; kc += 64) {
        const int buf = ((kc - kbase) >> 6) & 1;
        if (kc + 64 < kend) {
            attn_stage(sbase, buf ^ 1, Kh_g, Kl_g, Vh_g, Vl_g, bh, kc + 64, tid);
            CP_WAIT1();
        } else {
            CP_WAIT0();
        }
        __syncthreads();
        const u32 db = sbase + buf * (ABUFE * 2);

        // ---- S = Q K^T (log2-domain logits) ----
        float s[8][4];
#pragma unroll
        for (int na = 0; na < 8; na++)
#pragma unroll
            for (int c = 0; c < 4; c++) s[na][c] = 0.f;

#pragma unroll
        for (int ks = 0; ks < 4; ks++) {
#pragma unroll
            for (int np = 0; np < 4; np++) {
                const u32 a = db + 2 * ((np * 16 + rK) * KP + ks * 16 + cK);
                u32 rh[4], rl[4];
                ldsm4(rh, a);
                ldsm4(rl, a + 2 * PS);
                u32 b0h[2] = {rh[0], rh[1]}, b1h[2] = {rh[2], rh[3]};
                u32 b0l[2] = {rl[0], rl[1]}, b1l[2] = {rl[2], rl[3]};
                mma_bf16(s[2*np],   qfh[ks], b0h);
                mma_bf16(s[2*np],   qfh[ks], b0l);
                mma_bf16(s[2*np],   qfl[ks], b0h);
                mma_bf16(s[2*np+1], qfh[ks], b1h);
                mma_bf16(s[2*np+1], qfh[ks], b1l);
                mma_bf16(s[2*np+1], qfl[ks], b1h);
            }
        }

        // ---- no-max softmax: P = 2^s, thread-local sums ----
#pragma unroll
        for (int na = 0; na < 8; na++) {
            s[na][0] = ex2(s[na][0]);
            s[na][1] = ex2(s[na][1]);
            s[na][2] = ex2(s[na][2]);
            s[na][3] = ex2(s[na][3]);
            l0 += s[na][0] + s[na][1];
            l1 += s[na][2] + s[na][3];
        }

        // ---- O += P V (P packed in registers) ----
#pragma unroll
        for (int ks = 0; ks < 4; ks++) {
            HL p0 = split2f(s[2*ks][0],   s[2*ks][1]);
            HL p1 = split2f(s[2*ks][2],   s[2*ks][3]);
            HL p2 = split2f(s[2*ks+1][0], s[2*ks+1][1]);
            HL p3 = split2f(s[2*ks+1][2], s[2*ks+1][3]);
            u32 aph[4] = {p0.h, p1.h, p2.h, p3.h};
            u32 apl[4] = {p0.l, p1.l, p2.l, p3.l};
#pragma unroll
            for (int np = 0; np < 4; np++) {
                const u32 a = db + 2 * (2 * PS + (ks * 16 + rV) * KP + np * 16 + cV);
                u32 rh[4], rl[4];
                ldsm4t(rh, a);
                ldsm4t(rl, a + 2 * PS);
                u32 b0h[2] = {rh[0], rh[1]}, b1h[2] = {rh[2], rh[3]};
                u32 b0l[2] = {rl[0], rl[1]}, b1l[2] = {rl[2], rl[3]};
                mma_bf16(o[2*np],   aph, b0h);
                mma_bf16(o[2*np],   aph, b0l);
                mma_bf16(o[2*np],   apl, b0h);
                mma_bf16(o[2*np+1], aph, b1h);
                mma_bf16(o[2*np+1], aph, b1l);
                mma_bf16(o[2*np+1], apl, b1h);
            }
        }
        __syncthreads();
    }

    // ---- epilogue: quad-reduce L, write unnormalized U (fp32) and L ----
    l0 += __shfl_xor_sync(0xffffffffu, l0, 1);
    l0 += __shfl_xor_sync(0xffffffffu, l0, 2);
    l1 += __shfl_xor_sync(0xffffffffu, l1, 1);
    l1 += __shfl_xor_sync(0xffffffffu, l1, 2);

    const int row0 = q0 + w16 + g;
    float* ub = U + (size_t)z * PROJN + ((size_t)bh * SEQ + row0) * DEPTH;
#pragma unroll
    for (int na = 0; na < 8; na++) {
        *(float2*)&ub[na * 8 + 2 * tig] = make_float2(o[na][0], o[na][1]);
        *(float2*)&ub[8 * DEPTH + na * 8 + 2 * tig] = make_float2(o[na][2], o[na][3]);
    }
    if (tig == 0) {
        L[(size_t)z * NBH * SEQ + bh * SEQ + row0] = l0;
        L[(size_t)z * NBH * SEQ + bh * SEQ + row0 + 8] = l1;
    }
}

// combine: o = (U0+U1)/(L0+L1), split to bf16 planes in merged [B,S,D] layout
__global__ void attn_combine(const float* __restrict__ U, const float* __restrict__ L,
                             u16* __restrict__ Oh, u16* __restrict__ Ol)
{
    const int idx = blockIdx.x * 256 + threadIdx.x;     // over PROJN/2 float2 units
    const int d2 = idx & 31;
    const int srow = (idx >> 5) & (SEQ - 1);
    const int bh = idx >> 16;
    float2 a = ((const float2*)U)[idx];
    float2 b = ((const float2*)(U + PROJN))[idx];
    const float l = L[bh * SEQ + srow] + L[NBH * SEQ + bh * SEQ + srow];
    const float inv = 1.f / l;
    HL r = split2f((a.x + b.x) * inv, (a.y + b.y) * inv);
    const size_t o = ((size_t)((bh >> 4) * SEQ + srow)) * D_MODEL + (bh & 15) * 64 + d2 * 2;
    *(u32*)&Oh[o] = r.h;
    *(u32*)&Ol[o] = r.l;
}

// ---------------------------------------------------------------------------
extern "C" void kernel_launch(void* const* d_in, const int* in_sizes, int n_in,
                              void* d_out, int out_size)
{
    const float* v  = (const float*)d_in[0];
    const float* k  = (const float*)d_in[1];
    const float* q  = (const float*)d_in[2];
    const float* wq = (const float*)d_in[3];
    const float* bq = (const float*)d_in[4];
    const float* wk = (const float*)d_in[5];
    const float* bk = (const float*)d_in[6];
    const float* wv = (const float*)d_in[7];
    const float* bv = (const float*)d_in[8];
    const float* wo = (const float*)d_in[9];
    const float* bo = (const float*)d_in[10];
    float* out = (float*)d_out;

    u16 *xh, *xl, *wh, *wl, *ph, *pl, *oh, *ol;
    float *u, *lsum;
    cudaGetSymbolAddress((void**)&xh, g_xh);
    cudaGetSymbolAddress((void**)&xl, g_xl);
    cudaGetSymbolAddress((void**)&wh, g_wh);
    cudaGetSymbolAddress((void**)&wl, g_wl);
    cudaGetSymbolAddress((void**)&ph, g_ph);
    cudaGetSymbolAddress((void**)&pl, g_pl);
    cudaGetSymbolAddress((void**)&oh, g_oh);
    cudaGetSymbolAddress((void**)&ol, g_ol);
    cudaGetSymbolAddress((void**)&u,  g_u);
    cudaGetSymbolAddress((void**)&lsum, g_l);

    const int gemm_smem = 2 * GBUF * 2;    // 75776 B
    const int attn_smem = 2 * ABUFE * 2;   // 73728 B
    cudaFuncSetAttribute(gemm_proj, cudaFuncAttributeMaxDynamicSharedMemorySize, gemm_smem);
    cudaFuncSetAttribute(gemm_out,  cudaFuncAttributeMaxDynamicSharedMemorySize, gemm_smem);
    cudaFuncSetAttribute(attn_tc,   cudaFuncAttributeMaxDynamicSharedMemorySize, attn_smem);

    // 1) split inputs and weights
    split3_kernel<<<dim3(1024, 1, 3), 256>>>((const float4*)q, (const float4*)k,
                                             (const float4*)v,
                                             (uint2*)xh, (uint2*)xl, INN / 4);
    split4_kernel<<<dim3(512, 1, 4), 256>>>((const float4*)wq, (const float4*)wk,
                                            (const float4*)wv, (const float4*)wo,
                                            (uint2*)wh, (uint2*)wl, WN / 4);

    // 2) fused Q/K/V projections (one launch, grid.z = 3)
    gemm_proj<<<dim3(D_MODEL / 128, MROWS / 128, 3), 256, gemm_smem>>>(
        xh, xl, wh, wl, bq, bk, bv, ph, pl);

    // 3) attention, split-K over 2 key halves, then combine
    attn_tc<<<dim3(SEQ / 128, NBH, 2), 256, attn_smem>>>(
        ph, pl,
        ph + (size_t)PROJN, pl + (size_t)PROJN,
        ph + (size_t)2*PROJN, pl + (size_t)2*PROJN,
        u, lsum);
    attn_combine<<<PROJN / 2 / 256, 256>>>(u, lsum, oh, ol);

    // 4) output projection -> fp32 d_out
    gemm_out<<<dim3(D_MODEL / 128, MROWS / 128), 256, gemm_smem>>>(
        oh, ol, wh + (size_t)3*WN, wl + (size_t)3*WN, bo, out);
}

// round 13
// speedup vs baseline: 1.0256x; 1.0256x over previous
#include <cuda_runtime.h>
#include <cuda_bf16.h>
#include <math.h>

typedef unsigned int u32;
typedef unsigned short u16;

#define D_MODEL 1024
#define NHEAD   16
#define DEPTH   64
#define BATCH   4
#define SEQ     2048
#define MROWS   (BATCH * SEQ)       // 8192
#define NBH     (BATCH * NHEAD)     // 64
#define INN     (MROWS * D_MODEL)   // 8388608
#define WN      (D_MODEL * D_MODEL)
#define PROJN   (NBH * SEQ * DEPTH) // 8388608
#define QSCALE  (0.125f * 1.44269504088896341f)   // 1/sqrt(64) * log2(e)

// ---------------- global scratch (alloc-free rule) -------------------------
__device__ u16 g_xh[3][INN],  g_xl[3][INN];    // split q/k/v inputs
__device__ u16 g_wh[4][WN],   g_wl[4][WN];     // split wq/wk/wv/wo [k][n]
__device__ u16 g_ph[3][PROJN], g_pl[3][PROJN]; // projected qh/kh/vh planes
__device__ u16 g_oh[INN],     g_ol[INN];       // attention output planes

// ---------------- primitives ----------------------------------------------
__device__ __forceinline__ void mma_bf16(float c[4], const u32 a[4], const u32 b[2])
{
    asm("mma.sync.aligned.m16n8k16.row.col.f32.bf16.bf16.f32 "
        "{%0,%1,%2,%3}, {%4,%5,%6,%7}, {%8,%9}, {%0,%1,%2,%3};"
        : "+f"(c[0]), "+f"(c[1]), "+f"(c[2]), "+f"(c[3])
        : "r"(a[0]), "r"(a[1]), "r"(a[2]), "r"(a[3]), "r"(b[0]), "r"(b[1]));
}

struct HL { u32 h, l; };
__device__ __forceinline__ HL split2f(float x, float y)
{
    HL r;
    asm("cvt.rn.bf16x2.f32 %0, %1, %2;" : "=r"(r.h) : "f"(y), "f"(x));
    float xh = __uint_as_float(r.h << 16);
    float yh = __uint_as_float(r.h & 0xffff0000u);
    asm("cvt.rn.bf16x2.f32 %0, %1, %2;" : "=r"(r.l) : "f"(y - yh), "f"(x - xh));
    return r;
}

__device__ __forceinline__ float ex2(float x)
{
    float y;
    asm("ex2.approx.ftz.f32 %0, %1;" : "=f"(y) : "f"(x));
    return y;
}

__device__ __forceinline__ void ldsm4(u32 r[4], u32 a)
{
    asm volatile("ldmatrix.sync.aligned.m8n8.x4.shared.b16 {%0,%1,%2,%3}, [%4];"
        : "=r"(r[0]), "=r"(r[1]), "=r"(r[2]), "=r"(r[3]) : "r"(a));
}
__device__ __forceinline__ void ldsm4t(u32 r[4], u32 a)
{
    asm volatile("ldmatrix.sync.aligned.m8n8.x4.trans.shared.b16 {%0,%1,%2,%3}, [%4];"
        : "=r"(r[0]), "=r"(r[1]), "=r"(r[2]), "=r"(r[3]) : "r"(a));
}
__device__ __forceinline__ void cpa16(u32 s, const void* g)
{
    asm volatile("cp.async.ca.shared.global [%0], [%1], 16;" :: "r"(s), "l"(g));
}
#define CP_COMMIT() asm volatile("cp.async.commit_group;" ::: "memory")
#define CP_WAIT0()  asm volatile("cp.async.wait_group 0;" ::: "memory")

// ---------------- split pre-pass (all 7 tensors, one launch) ----------------
__global__ void split7_kernel(const float4* __restrict__ q,
                              const float4* __restrict__ k,
                              const float4* __restrict__ v,
                              const float4* __restrict__ wq,
                              const float4* __restrict__ wk,
                              const float4* __restrict__ wv,
                              const float4* __restrict__ wo,
                              uint2* __restrict__ xh, uint2* __restrict__ xl,
                              uint2* __restrict__ wh, uint2* __restrict__ wl)
{
    const int z = blockIdx.z;
    const float4* src;
    uint2 *h, *l;
    int n4;
    if (z < 3) {
        src = (z == 0) ? q : (z == 1) ? k : v;
        n4 = INN / 4;
        h = xh + (size_t)z * n4;
        l = xl + (size_t)z * n4;
    } else {
        const int w = z - 3;
        src = (w == 0) ? wq : (w == 1) ? wk : (w == 2) ? wv : wo;
        n4 = WN / 4;
        h = wh + (size_t)w * n4;
        l = wl + (size_t)w * n4;
    }
    int i = blockIdx.x * blockDim.x + threadIdx.x;
    const int stride = gridDim.x * blockDim.x;
    for (; i < n4; i += stride) {
        float4 val = src[i];
        HL a = split2f(val.x, val.y), b = split2f(val.z, val.w);
        h[i] = make_uint2(a.h, b.h);
        l[i] = make_uint2(a.l, b.l);
    }
}

// ---------------- GEMM core (HMMA, 2-stage, single-barrier) -----------------
// 128x128 tile, BK=32, 8 warps (2m x 4n). A [m][k] pitch 40; W [k][n] pitch 136.
#define BKP 40
#define NPW 136
#define ASZ (128 * BKP)               // 5120
#define WSZ (32 * NPW)                // 4352
#define GBUF (2 * ASZ + 2 * WSZ)      // 18944 elems per buffer

__device__ __forceinline__ void gemm_stage(
    u32 sbase, int buf,
    const u16* __restrict__ Ah_g, const u16* __restrict__ Al_g,
    const u16* __restrict__ Wh_g, const u16* __restrict__ Wl_g,
    int m0, int n0, int kt, int tid)
{
    const u32 db = sbase + buf * (GBUF * 2);
    const int a_row = tid >> 2, a_off = tid & 3;
    const int w_row = tid >> 4, w_off = tid & 15;
#pragma unroll
    for (int i = 0; i < 4; i++) {
        const u16* src = (i < 2) ? Ah_g : Al_g;
        const int row = a_row + 64 * (i & 1);
        cpa16(db + 2 * ((i >> 1) * ASZ + row * BKP + a_off * 8),
              src + (size_t)(m0 + row) * D_MODEL + kt * 32 + a_off * 8);
    }
#pragma unroll
    for (int i = 0; i < 4; i++) {
        const u16* src = (i < 2) ? Wh_g : Wl_g;
        const int row = w_row + 16 * (i & 1);
        cpa16(db + 2 * (2 * ASZ + (i >> 1) * WSZ + row * NPW + w_off * 8),
              src + (size_t)(kt * 32 + row) * D_MODEL + n0 + w_off * 8);
    }
    CP_COMMIT();
}

template <int MODE>
__device__ __forceinline__ void gemm_body(
    const u16* __restrict__ Ah_g, const u16* __restrict__ Al_g,
    const u16* __restrict__ Wh_g, const u16* __restrict__ Wl_g,
    const float* __restrict__ bias, float scale,
    float* __restrict__ Cf, u16* __restrict__ Ch, u16* __restrict__ Cl)
{
    extern __shared__ u16 smw[];
    const u32 sbase = (u32)__cvta_generic_to_shared(smw);

    const int m0 = blockIdx.y * 128, n0 = blockIdx.x * 128;
    const int tid = threadIdx.x, lane = tid & 31, warp = tid >> 5;
    const int g = lane >> 2, tig = lane & 3;
    const int wm = warp >> 2, wn = warp & 3;

    const int rA = wm * 64 + (lane & 7) + ((lane >> 3) & 1) * 8;
    const int cA = (lane >> 4) * 8;
    const int rW = ((lane >> 3) & 1) * 8 + (lane & 7);
    const int cW = wn * 32 + (lane >> 4) * 8;

    float acc[4][4][4];
#pragma unroll
    for (int i = 0; i < 4; i++)
#pragma unroll
        for (int j = 0; j < 4; j++)
#pragma unroll
            for (int c = 0; c < 4; c++) acc[i][j][c] = 0.f;

    gemm_stage(sbase, 0, Ah_g, Al_g, Wh_g, Wl_g, m0, n0, 0, tid);

    for (int kt = 0; kt < 32; kt++) {
        const int buf = kt & 1;
        // wait for this iteration's data; barrier also proves all warps
        // finished reading buf^1 last iteration -> restaging it is safe.
        CP_WAIT0();
        __syncthreads();
        if (kt < 31)
            gemm_stage(sbase, buf ^ 1, Ah_g, Al_g, Wh_g, Wl_g, m0, n0, kt + 1, tid);

        const u32 db = sbase + buf * (GBUF * 2);
#pragma unroll
        for (int kk = 0; kk < 2; kk++) {
            u32 ah[4][4], al_[4][4];
#pragma unroll
            for (int ma = 0; ma < 4; ma++) {
                const u32 a = db + 2 * ((rA + ma * 16) * BKP + kk * 16 + cA);
                ldsm4(ah[ma], a);
                ldsm4(al_[ma], a + 2 * ASZ);
            }
            u32 bh[4][2], bl[4][2];
#pragma unroll
            for (int np = 0; np < 2; np++) {
                const u32 a = db + 2 * (2 * ASZ + (kk * 16 + rW) * NPW + cW + np * 16);
                u32 r[4];
                ldsm4t(r, a);
                bh[2*np][0] = r[0]; bh[2*np][1] = r[1];
                bh[2*np+1][0] = r[2]; bh[2*np+1][1] = r[3];
                ldsm4t(r, a + 2 * WSZ);
                bl[2*np][0] = r[0]; bl[2*np][1] = r[1];
                bl[2*np+1][0] = r[2]; bl[2*np+1][1] = r[3];
            }
#pragma unroll
            for (int ma = 0; ma < 4; ma++)
#pragma unroll
                for (int na = 0; na < 4; na++) {
                    mma_bf16(acc[ma][na], ah[ma], bh[na]);
                    mma_bf16(acc[ma][na], ah[ma], bl[na]);
                    mma_bf16(acc[ma][na], al_[ma], bh[na]);
                }
        }
    }

#pragma unroll
    for (int ma = 0; ma < 4; ma++) {
        const int m_r = m0 + wm * 64 + ma * 16 + g;
#pragma unroll
        for (int na = 0; na < 4; na++) {
            const int n = n0 + wn * 32 + na * 8 + 2 * tig;
            const float2 bv = *(const float2*)&bias[n];
            const float o0 = (acc[ma][na][0] + bv.x) * scale;
            const float o1 = (acc[ma][na][1] + bv.y) * scale;
            const float o2 = (acc[ma][na][2] + bv.x) * scale;
            const float o3 = (acc[ma][na][3] + bv.y) * scale;
            if (MODE == 0) {
                *(float2*)&Cf[(size_t)m_r * D_MODEL + n] = make_float2(o0, o1);
                *(float2*)&Cf[(size_t)(m_r + 8) * D_MODEL + n] = make_float2(o2, o3);
            } else {
                const int h = n >> 6, d = n & 63;
                const int b = m_r >> 11, s = m_r & 2047;
                const size_t i0 = (((size_t)(b * NHEAD + h)) * SEQ + s) * DEPTH + d;
                const size_t i1 = i0 + 8 * DEPTH;
                HL r0 = split2f(o0, o1), r1 = split2f(o2, o3);
                *(u32*)&Ch[i0] = r0.h; *(u32*)&Cl[i0] = r0.l;
                *(u32*)&Ch[i1] = r1.h; *(u32*)&Cl[i1] = r1.l;
            }
        }
    }
}

__global__ void __launch_bounds__(256, 2) gemm_proj(
    const u16* __restrict__ xh, const u16* __restrict__ xl,
    const u16* __restrict__ wh, const u16* __restrict__ wl,
    const float* __restrict__ bq, const float* __restrict__ bk,
    const float* __restrict__ bv,
    u16* __restrict__ ph, u16* __restrict__ pl)
{
    const int z = blockIdx.z;
    const float* bias = (z == 0) ? bq : (z == 1) ? bk : bv;
    gemm_body<1>(xh + (size_t)z * INN, xl + (size_t)z * INN,
                 wh + (size_t)z * WN,  wl + (size_t)z * WN,
                 bias, (z == 0) ? QSCALE : 1.f,
                 nullptr, ph + (size_t)z * PROJN, pl + (size_t)z * PROJN);
}

__global__ void __launch_bounds__(256, 2) gemm_out(
    const u16* __restrict__ Ah, const u16* __restrict__ Al,
    const u16* __restrict__ Wh, const u16* __restrict__ Wl,
    const float* __restrict__ bias, float* __restrict__ Cf)
{
    gemm_body<0>(Ah, Al, Wh, Wl, bias, 1.f, Cf, nullptr, nullptr);
}

// ---------------- flash attention (HMMA, no-max softmax, 1-barrier) ---------
#define KP  72
#define PS  (64 * KP)
#define ABUFE (4 * PS)

__device__ __forceinline__ void attn_stage(
    u32 sbase, int buf,
    const u16* __restrict__ Kh_g, const u16* __restrict__ Kl_g,
    const u16* __restrict__ Vh_g, const u16* __restrict__ Vl_g,
    int bh, int kc, int tid)
{
    const u32 db = sbase + buf * (ABUFE * 2);
#pragma unroll
    for (int i = 0; i < 8; i++) {
        const int plane = i >> 1;
        const u16* src = (plane == 0) ? Kh_g : (plane == 1) ? Kl_g
                       : (plane == 2) ? Vh_g : Vl_g;
        const int row = (tid >> 3) + 32 * (i & 1);
        cpa16(db + 2 * (plane * PS + row * KP + (tid & 7) * 8),
              src + ((size_t)bh * SEQ + kc + row) * DEPTH + (tid & 7) * 8);
    }
    CP_COMMIT();
}

__global__ void __launch_bounds__(256, 2) attn_tc(
    const u16* __restrict__ Qh_g, const u16* __restrict__ Ql_g,
    const u16* __restrict__ Kh_g, const u16* __restrict__ Kl_g,
    const u16* __restrict__ Vh_g, const u16* __restrict__ Vl_g,
    u16* __restrict__ Oh, u16* __restrict__ Ol)
{
    extern __shared__ u16 sma[];
    const u32 sbase = (u32)__cvta_generic_to_shared(sma);

    const int bh = blockIdx.y, q0 = blockIdx.x * 128;
    const int tid = threadIdx.x, lane = tid & 31, warp = tid >> 5;
    const int g = lane >> 2, tig = lane & 3;
    const int w16 = warp * 16;

    u32 qfh[4][4], qfl[4][4];
    {
        const u16* Qbh = Qh_g + ((size_t)bh * SEQ + q0) * DEPTH;
        const u16* Qbl = Ql_g + ((size_t)bh * SEQ + q0) * DEPTH;
#pragma unroll
        for (int ks = 0; ks < 4; ks++) {
            const int c = ks * 16 + 2 * tig;
            qfh[ks][0] = *(const u32*)&Qbh[(w16 + g) * DEPTH + c];
            qfh[ks][1] = *(const u32*)&Qbh[(w16 + g + 8) * DEPTH + c];
            qfh[ks][2] = *(const u32*)&Qbh[(w16 + g) * DEPTH + c + 8];
            qfh[ks][3] = *(const u32*)&Qbh[(w16 + g + 8) * DEPTH + c + 8];
            qfl[ks][0] = *(const u32*)&Qbl[(w16 + g) * DEPTH + c];
            qfl[ks][1] = *(const u32*)&Qbl[(w16 + g + 8) * DEPTH + c];
            qfl[ks][2] = *(const u32*)&Qbl[(w16 + g) * DEPTH + c + 8];
            qfl[ks][3] = *(const u32*)&Qbl[(w16 + g + 8) * DEPTH + c + 8];
        }
    }

    float o[8][4];
#pragma unroll
    for (int na = 0; na < 8; na++)
#pragma unroll
        for (int c = 0; c < 4; c++) o[na][c] = 0.f;
    float l0 = 0.f, l1 = 0.f;      // thread-local exp sums (quad-reduced at end)

    const int rK = (lane >> 4) * 8 + (lane & 7);
    const int cK = ((lane >> 3) & 1) * 8;
    const int rV = ((lane >> 3) & 1) * 8 + (lane & 7);
    const int cV = (lane >> 4) * 8;

    attn_stage(sbase, 0, Kh_g, Kl_g, Vh_g, Vl_g, bh, 0, tid);

    for (int kc = 0; kc < SEQ; kc += 64) {
        const int buf = (kc >> 6) & 1;
        CP_WAIT0();
        __syncthreads();     // data visible + all warps done reading buf^1
        if (kc + 64 < SEQ)
            attn_stage(sbase, buf ^ 1, Kh_g, Kl_g, Vh_g, Vl_g, bh, kc + 64, tid);

        const u32 db = sbase + buf * (ABUFE * 2);

        // ---- S = Q K^T (log2-domain logits) ----
        float s[8][4];
#pragma unroll
        for (int na = 0; na < 8; na++)
#pragma unroll
            for (int c = 0; c < 4; c++) s[na][c] = 0.f;

#pragma unroll
        for (int ks = 0; ks < 4; ks++) {
#pragma unroll
            for (int np = 0; np < 4; np++) {
                const u32 a = db + 2 * ((np * 16 + rK) * KP + ks * 16 + cK);
                u32 rh[4], rl[4];
                ldsm4(rh, a);
                ldsm4(rl, a + 2 * PS);
                u32 b0h[2] = {rh[0], rh[1]}, b1h[2] = {rh[2], rh[3]};
                u32 b0l[2] = {rl[0], rl[1]}, b1l[2] = {rl[2], rl[3]};
                mma_bf16(s[2*np],   qfh[ks], b0h);
                mma_bf16(s[2*np],   qfh[ks], b0l);
                mma_bf16(s[2*np],   qfl[ks], b0h);
                mma_bf16(s[2*np+1], qfh[ks], b1h);
                mma_bf16(s[2*np+1], qfh[ks], b1l);
                mma_bf16(s[2*np+1], qfl[ks], b1h);
            }
        }

        // ---- no-max softmax: P = 2^s, thread-local sums, no shuffles ----
#pragma unroll
        for (int na = 0; na < 8; na++) {
            s[na][0] = ex2(s[na][0]);
            s[na][1] = ex2(s[na][1]);
            s[na][2] = ex2(s[na][2]);
            s[na][3] = ex2(s[na][3]);
            l0 += s[na][0] + s[na][1];
            l1 += s[na][2] + s[na][3];
        }

        // ---- O += P V (P packed in registers) ----
#pragma unroll
        for (int ks = 0; ks < 4; ks++) {
            HL p0 = split2f(s[2*ks][0],   s[2*ks][1]);
            HL p1 = split2f(s[2*ks][2],   s[2*ks][3]);
            HL p2 = split2f(s[2*ks+1][0], s[2*ks+1][1]);
            HL p3 = split2f(s[2*ks+1][2], s[2*ks+1][3]);
            u32 aph[4] = {p0.h, p1.h, p2.h, p3.h};
            u32 apl[4] = {p0.l, p1.l, p2.l, p3.l};
#pragma unroll
            for (int np = 0; np < 4; np++) {
                const u32 a = db + 2 * (2 * PS + (ks * 16 + rV) * KP + np * 16 + cV);
                u32 rh[4], rl[4];
                ldsm4t(rh, a);
                ldsm4t(rl, a + 2 * PS);
                u32 b0h[2] = {rh[0], rh[1]}, b1h[2] = {rh[2], rh[3]};
                u32 b0l[2] = {rl[0], rl[1]}, b1l[2] = {rl[2], rl[3]};
                mma_bf16(o[2*np],   aph, b0h);
                mma_bf16(o[2*np],   aph, b0l);
                mma_bf16(o[2*np],   apl, b0h);
                mma_bf16(o[2*np+1], aph, b1h);
                mma_bf16(o[2*np+1], aph, b1l);
                mma_bf16(o[2*np+1], apl, b1h);
            }
        }
    }

    // ---- epilogue: quad-reduce l, normalize, write bf16 planes ----
    l0 += __shfl_xor_sync(0xffffffffu, l0, 1);
    l0 += __shfl_xor_sync(0xffffffffu, l0, 2);
    l1 += __shfl_xor_sync(0xffffffffu, l1, 1);
    l1 += __shfl_xor_sync(0xffffffffu, l1, 2);

    const int b = bh >> 4, h = bh & 15;
    const float i0 = 1.f / l0, i1 = 1.f / l1;
    const int row0 = q0 + w16 + g;
    const size_t base0 = ((size_t)(b * SEQ + row0)) * D_MODEL + h * 64 + 2 * tig;
    const size_t base1 = base0 + (size_t)8 * D_MODEL;
#pragma unroll
    for (int na = 0; na < 8; na++) {
        HL r0 = split2f(o[na][0] * i0, o[na][1] * i0);
        HL r1 = split2f(o[na][2] * i1, o[na][3] * i1);
        *(u32*)&Oh[base0 + na * 8] = r0.h;
        *(u32*)&Ol[base0 + na * 8] = r0.l;
        *(u32*)&Oh[base1 + na * 8] = r1.h;
        *(u32*)&Ol[base1 + na * 8] = r1.l;
    }
}

// ---------------------------------------------------------------------------
extern "C" void kernel_launch(void* const* d_in, const int* in_sizes, int n_in,
                              void* d_out, int out_size)
{
    const float* v  = (const float*)d_in[0];
    const float* k  = (const float*)d_in[1];
    const float* q  = (const float*)d_in[2];
    const float* wq = (const float*)d_in[3];
    const float* bq = (const float*)d_in[4];
    const float* wk = (const float*)d_in[5];
    const float* bk = (const float*)d_in[6];
    const float* wv = (const float*)d_in[7];
    const float* bv = (const float*)d_in[8];
    const float* wo = (const float*)d_in[9];
    const float* bo = (const float*)d_in[10];
    float* out = (float*)d_out;

    u16 *xh, *xl, *wh, *wl, *ph, *pl, *oh, *ol;
    cudaGetSymbolAddress((void**)&xh, g_xh);
    cudaGetSymbolAddress((void**)&xl, g_xl);
    cudaGetSymbolAddress((void**)&wh, g_wh);
    cudaGetSymbolAddress((void**)&wl, g_wl);
    cudaGetSymbolAddress((void**)&ph, g_ph);
    cudaGetSymbolAddress((void**)&pl, g_pl);
    cudaGetSymbolAddress((void**)&oh, g_oh);
    cudaGetSymbolAddress((void**)&ol, g_ol);

    const int gemm_smem = 2 * GBUF * 2;    // 75776 B
    const int attn_smem = 2 * ABUFE * 2;   // 73728 B
    cudaFuncSetAttribute(gemm_proj, cudaFuncAttributeMaxDynamicSharedMemorySize, gemm_smem);
    cudaFuncSetAttribute(gemm_out,  cudaFuncAttributeMaxDynamicSharedMemorySize, gemm_smem);
    cudaFuncSetAttribute(attn_tc,   cudaFuncAttributeMaxDynamicSharedMemorySize, attn_smem);

    // 1) split all inputs and weights (one launch, grid.z = 7)
    split7_kernel<<<dim3(512, 1, 7), 256>>>(
        (const float4*)q, (const float4*)k, (const float4*)v,
        (const float4*)wq, (const float4*)wk, (const float4*)wv, (const float4*)wo,
        (uint2*)xh, (uint2*)xl, (uint2*)wh, (uint2*)wl);

    // 2) fused Q/K/V projections (one launch, grid.z = 3)
    gemm_proj<<<dim3(D_MODEL / 128, MROWS / 128, 3), 256, gemm_smem>>>(
        xh, xl, wh, wl, bq, bk, bv, ph, pl);

    // 3) attention
    attn_tc<<<dim3(SEQ / 128, NBH), 256, attn_smem>>>(
        ph, pl,
        ph + (size_t)PROJN, pl + (size_t)PROJN,
        ph + (size_t)2*PROJN, pl + (size_t)2*PROJN,
        oh, ol);

    // 4) output projection -> fp32 d_out
    gemm_out<<<dim3(D_MODEL / 128, MROWS / 128), 256, gemm_smem>>>(
        oh, ol, wh + (size_t)3*WN, wl + (size_t)3*WN, bo, out);
}